// round 14
// baseline (speedup 1.0000x reference)
#include <cuda_runtime.h>
#include <cstdint>

#define BB 128
#define TT 256
#define II 64
#define HH 1024
#define OO 64
#define NCTA 148
#define NTH 256
#define KC 32

#if defined(__CUDA_ARCH_FEAT_SM103_ALL) || defined(__CUDA_ARCH_SPECIFIC__)
#define HAS_TCGEN05 1
#else
#define HAS_TCGEN05 0
#endif

// smem: [0]=tmem ptr, [8]=mbar0, [16]=mbar1, [24]=mbar2
// buffer i at 1024 + i*65536: Ahi +0, Alo +16384, Bhi +32768, Blo +49152
#define SMEM_BYTES 197632

// ---------------- persistent device globals (zero-initialized) -------------
__device__ float bufH1[BB * HH];        // h1 [b][j]
__device__ float bufH2[BB * HH];        // h2 [b][j]
__device__ float g_u[BB * HH];          // gate [b][j]
__device__ float pH1[6 * BB * HH];      // h1pre slices (T1)
__device__ float pG [14 * BB * HH];     // gate: 0-5 T2 (h2), 6-13 T6 (h1)
__device__ float pH2[14 * BB * HH];     // h2pre: 0-4 T3 (h2), 5-13 T5 (h1)
__device__ float pO [16 * BB * OO];     // out: 0-7 T4 (Wo2*h2), 8-15 T7 (Wo1*h1)
__device__ volatile unsigned g_flags[NCTA * 32];
__device__ unsigned g_epoch_base;

// chunk-range tables
__constant__ int cT1[7] = {0, 5, 11, 17, 22, 28, 34};   // 34 chunks, 6 slices
__constant__ int cT2[7] = {0, 5, 10, 16, 21, 26, 32};   // 32 chunks, 6 slices
__constant__ int cT3[6] = {0, 6, 12, 19, 25, 32};       // 32 chunks, 5 slices
__constant__ int cT5[10] = {0, 3, 7, 10, 14, 17, 21, 24, 28, 32}; // 9 slices

// ---------------------------------------------------------------------------
__device__ __forceinline__ uint32_t cvta_s(const void* p) {
    uint32_t a;
    asm("{ .reg .u64 t; cvta.to.shared.u64 t, %1; cvt.u32.u64 %0, t; }"
        : "=r"(a) : "l"(p));
    return a;
}

__device__ __forceinline__ bool elect1() {
    uint32_t p;
    asm volatile("{ .reg .pred p; elect.sync _|p, 0xFFFFFFFF; selp.b32 %0, 1, 0, p; }"
                 : "=r"(p));
    return p != 0;
}

__device__ __forceinline__ uint64_t sdesc(uint32_t addr) {
    // SW128 (2<<61) | version(1<<46) | SBO=64<<32 | LBO=1<<16
    return 0x4000404000010000ull | ((uint64_t)(addr >> 4) & 0x3FFF);
}

__device__ __forceinline__ void mbar_wait(uint32_t mbar, uint32_t parity) {
    asm volatile(
        "{\n\t.reg .pred P;\n\t"
        "WL%=:\n\t"
        "mbarrier.try_wait.parity.acquire.cta.shared::cta.b64 P, [%0], %1, 0x989680;\n\t"
        "@!P bra WL%=;\n\t}"
        :: "r"(mbar), "r"(parity) : "memory");
}

__device__ __forceinline__ void gsync(unsigned &epoch, int u, int tid) {
    __syncthreads();
    epoch++;
    __threadfence();
    if (tid == 0) g_flags[u * 32] = epoch;
    for (int i = tid; i < NCTA; i += NTH)
        while (g_flags[i * 32] < epoch) { }
    __syncthreads();
    __threadfence();
}

__device__ __forceinline__ void split_f4(float4 v, float4 &hi, float4 &lo) {
    hi.x = __uint_as_float(__float_as_uint(v.x) & 0xFFFFE000u); lo.x = v.x - hi.x;
    hi.y = __uint_as_float(__float_as_uint(v.y) & 0xFFFFE000u); lo.y = v.y - hi.y;
    hi.z = __uint_as_float(__float_as_uint(v.z) & 0xFFFFE000u); lo.z = v.z - hi.z;
    hi.w = __uint_as_float(__float_as_uint(v.w) & 0xFFFFE000u); lo.w = v.w - hi.w;
}

#if HAS_TCGEN05
#define LDTM32(r, a) \
    asm volatile( \
        "tcgen05.ld.sync.aligned.32x32b.x32.b32 " \
        "{%0, %1, %2, %3, %4, %5, %6, %7, " \
        " %8, %9, %10, %11, %12, %13, %14, %15, " \
        " %16, %17, %18, %19, %20, %21, %22, %23, " \
        " %24, %25, %26, %27, %28, %29, %30, %31}, [%32];" \
        : "=r"((r)[0]),  "=r"((r)[1]),  "=r"((r)[2]),  "=r"((r)[3]), \
          "=r"((r)[4]),  "=r"((r)[5]),  "=r"((r)[6]),  "=r"((r)[7]), \
          "=r"((r)[8]),  "=r"((r)[9]),  "=r"((r)[10]), "=r"((r)[11]), \
          "=r"((r)[12]), "=r"((r)[13]), "=r"((r)[14]), "=r"((r)[15]), \
          "=r"((r)[16]), "=r"((r)[17]), "=r"((r)[18]), "=r"((r)[19]), \
          "=r"((r)[20]), "=r"((r)[21]), "=r"((r)[22]), "=r"((r)[23]), \
          "=r"((r)[24]), "=r"((r)[25]), "=r"((r)[26]), "=r"((r)[27]), \
          "=r"((r)[28]), "=r"((r)[29]), "=r"((r)[30]), "=r"((r)[31]) \
        : "r"(a))

__device__ __forceinline__ void mma_tf32(uint32_t tmem, uint64_t a, uint64_t b,
                                         uint32_t idesc, uint32_t en) {
    asm volatile(
        "{\n\t.reg .pred p;\n\t"
        "setp.ne.u32 p, %4, 0;\n\t"
        "tcgen05.mma.cta_group::1.kind::tf32 [%0], %1, %2, %3, "
        "{%5, %5, %5, %5}, p;\n\t}"
        :: "r"(tmem), "l"(a), "l"(b), "r"(idesc), "r"(en), "r"(0u)
        : "memory");
}
#endif

// ---------------------------------------------------------------------------
// Batched loads for one chunk: A 128 x 32, B NN x 32 (float4 granules).
template<int NN>
__device__ __forceinline__ void ldg_chunk(
    int c, int splitc,
    const float* __restrict__ A0, int lda0,
    const float* __restrict__ A1, int lda1,
    const float* __restrict__ B0, int ldb0,
    const float* __restrict__ B1, int ldb1,
    int tid, float4 (&va)[4], float4 (&vb)[NN / 32])
{
    const float* Ap; int la;
    const float* Bp; int lb;
    if (c < splitc) { Ap = A0 + c * KC;            la = lda0;
                      Bp = B0 + c * KC;            lb = ldb0; }
    else            { Ap = A1 + (c - splitc) * KC; la = lda1;
                      Bp = B1 + (c - splitc) * KC; lb = ldb1; }
    #pragma unroll
    for (int r = 0; r < 4; r++) {               // A: 1024 float4 / 256
        int i = tid + r * NTH;
        int rr = i >> 3, c4 = i & 7;
        va[r] = __ldcg(reinterpret_cast<const float4*>(Ap + (size_t)rr * la + c4 * 4));
    }
    #pragma unroll
    for (int r = 0; r < NN / 32; r++) {         // B: NN*8 float4 / 256
        int i = tid + r * NTH;
        int rr = i >> 3, c4 = i & 7;
        vb[r] = *reinterpret_cast<const float4*>(Bp + (size_t)rr * lb + c4 * 4);
    }
}

// ---------------------------------------------------------------------------
// Split-K unit: D[b=128][NN j] += A[128 x 32k-chunks] @ B[NN x ...]^T, 3xTF32.
// Kc=32 chunks, 3-deep smem pipeline, register prefetch.
template<int NN>
__device__ __forceinline__ void run_unit(
    int c0, int c1, int splitc,
    const float* __restrict__ A0, int lda0,
    const float* __restrict__ A1, int lda1,
    const float* __restrict__ B0, int ldb0,
    const float* __restrict__ B1, int ldb1,
    uint32_t sb, float* __restrict__ smf, uint32_t tmem,
    float* __restrict__ dst, int ldd,
    int tid, uint32_t* committed, uint32_t* waited)
{
#if HAS_TCGEN05
    (void)smf;
    const uint32_t idesc = (NN == 128) ? 0x8200910u : 0x8100910u;
    float4 va[4], vb[NN / 32];
    ldg_chunk<NN>(c0, splitc, A0, lda0, A1, lda1, B0, ldb0, B1, ldb1, tid, va, vb);

    for (int c = c0; c < c1; c++) {
        const int b = (c - c0) % 3;
        const uint32_t mbar = sb + 8 + b * 8;
        if (committed[b] > waited[b]) {          // buffer owned by MMA c-3
            mbar_wait(mbar, waited[b] & 1);
            waited[b]++;
        }
        const uint32_t sA = sb + 1024 + b * 65536;
        const uint32_t sB = sA + 32768;

        // ---- STS current chunk from registers (split hi/lo) ----
        #pragma unroll
        for (int r = 0; r < 4; r++) {
            int i = tid + r * NTH;
            int rr = i >> 3, c4 = i & 7;
            float4 hi, lo;
            split_f4(va[r], hi, lo);
            int bo = ((rr >> 3) << 10) | ((rr & 7) << 7) | (c4 << 4);
            uint32_t sw = bo ^ ((bo >> 3) & 0x70);
            asm volatile("st.shared.v4.b32 [%0], {%1,%2,%3,%4};"
                :: "r"(sA + sw), "r"(__float_as_uint(hi.x)),
                   "r"(__float_as_uint(hi.y)), "r"(__float_as_uint(hi.z)),
                   "r"(__float_as_uint(hi.w)) : "memory");
            asm volatile("st.shared.v4.b32 [%0], {%1,%2,%3,%4};"
                :: "r"(sA + 16384 + sw), "r"(__float_as_uint(lo.x)),
                   "r"(__float_as_uint(lo.y)), "r"(__float_as_uint(lo.z)),
                   "r"(__float_as_uint(lo.w)) : "memory");
        }
        #pragma unroll
        for (int r = 0; r < NN / 32; r++) {
            int i = tid + r * NTH;
            int rr = i >> 3, c4 = i & 7;
            float4 hi, lo;
            split_f4(vb[r], hi, lo);
            int bo = ((rr >> 3) << 10) | ((rr & 7) << 7) | (c4 << 4);
            uint32_t sw = bo ^ ((bo >> 3) & 0x70);
            asm volatile("st.shared.v4.b32 [%0], {%1,%2,%3,%4};"
                :: "r"(sB + sw), "r"(__float_as_uint(hi.x)),
                   "r"(__float_as_uint(hi.y)), "r"(__float_as_uint(hi.z)),
                   "r"(__float_as_uint(hi.w)) : "memory");
            asm volatile("st.shared.v4.b32 [%0], {%1,%2,%3,%4};"
                :: "r"(sB + 16384 + sw), "r"(__float_as_uint(lo.x)),
                   "r"(__float_as_uint(lo.y)), "r"(__float_as_uint(lo.z)),
                   "r"(__float_as_uint(lo.w)) : "memory");
        }
        asm volatile("fence.proxy.async.shared::cta;" ::: "memory");
        __syncthreads();

        // ---- prefetch next chunk (overlaps MMA + next wait) ----
        if (c + 1 < c1)
            ldg_chunk<NN>(c + 1, splitc, A0, lda0, A1, lda1, B0, ldb0, B1, ldb1,
                          tid, va, vb);

        if (tid < 32 && elect1()) {
            uint64_t dahi = sdesc(sA), dalo = sdesc(sA + 16384);
            uint64_t dbhi = sdesc(sB), dblo = sdesc(sB + 16384);
            #pragma unroll
            for (int s = 0; s < 4; s++) {        // Kc=32 -> 4 steps of K=8
                uint64_t o = (uint64_t)(s << 1);
                mma_tf32(tmem, dahi + o, dbhi + o, idesc, (c > c0 || s > 0) ? 1u : 0u);
                mma_tf32(tmem, dahi + o, dblo + o, idesc, 1u);
                mma_tf32(tmem, dalo + o, dbhi + o, idesc, 1u);
            }
            asm volatile(
                "tcgen05.commit.cta_group::1.mbarrier::arrive::one.shared::cluster.b64 [%0];"
                :: "r"(mbar) : "memory");
        }
        committed[b]++;
    }
    #pragma unroll
    for (int b = 0; b < 3; b++) {
        if (committed[b] > waited[b]) {
            mbar_wait(sb + 8 + b * 8, waited[b] & 1);
            waited[b]++;
        }
    }
    asm volatile("tcgen05.fence::after_thread_sync;" ::: "memory");

    if (tid < 128) {
        uint32_t d[4][32];
        #pragma unroll
        for (int g = 0; g < NN / 32; g++) LDTM32(d[g], tmem + g * 32);
        asm volatile("tcgen05.wait::ld.sync.aligned;" ::: "memory");
        asm volatile("tcgen05.fence::before_thread_sync;" ::: "memory");

        float* drow = dst + (size_t)tid * ldd;   // row b == tid
        #pragma unroll
        for (int g = 0; g < NN / 32; g++)
            #pragma unroll
            for (int c4 = 0; c4 < 8; c4++)
                *reinterpret_cast<float4*>(drow + g * 32 + c4 * 4) = make_float4(
                    __uint_as_float(d[g][c4 * 4 + 0]), __uint_as_float(d[g][c4 * 4 + 1]),
                    __uint_as_float(d[g][c4 * 4 + 2]), __uint_as_float(d[g][c4 * 4 + 3]));
    }
    __syncthreads();
#else
    // ---------------- SIMT fallback (base-arch pass only; never selected) --
    (void)sb; (void)tmem; (void)committed; (void)waited;
    float acc[NN];
    #pragma unroll
    for (int j = 0; j < NN; j++) acc[j] = 0.f;
    for (int c = c0; c < c1; c++) {
        const float* Ap; int la;
        const float* Bp; int lb;
        if (c < splitc) { Ap = A0 + c * KC;            la = lda0;
                          Bp = B0 + c * KC;            lb = ldb0; }
        else            { Ap = A1 + (c - splitc) * KC; la = lda1;
                          Bp = B1 + (c - splitc) * KC; lb = ldb1; }
        for (int i = tid; i < NN * 8; i += NTH) {
            int r = i >> 3, c4 = i & 7;
            *reinterpret_cast<float4*>(smf + r * KC + c4 * 4) =
                *reinterpret_cast<const float4*>(Bp + (size_t)r * lb + c4 * 4);
        }
        __syncthreads();
        if (tid < 128) {
            const float* arow = Ap + (size_t)tid * la;
            for (int k = 0; k < KC; k++) {
                float a = arow[k];
                #pragma unroll
                for (int j = 0; j < NN; j++) acc[j] += a * smf[j * KC + k];
            }
        }
        __syncthreads();
    }
    if (tid < 128) {
        float* drow = dst + (size_t)tid * ldd;
        #pragma unroll
        for (int j = 0; j < NN; j += 4)
            *reinterpret_cast<float4*>(drow + j) =
                make_float4(acc[j], acc[j + 1], acc[j + 2], acc[j + 3]);
    }
    __syncthreads();
#endif
}

// ---------------------------------------------------------------------------
__global__ void __launch_bounds__(NTH, 1) k_rnn(
    const float* __restrict__ x,
    const float* __restrict__ Wih1, const float* __restrict__ bih1,
    const float* __restrict__ Whh1, const float* __restrict__ bhh1,
    const float* __restrict__ Wih2, const float* __restrict__ bih2,
    const float* __restrict__ Whh2, const float* __restrict__ bhh2,
    const float* __restrict__ Wg,   const float* __restrict__ bg,
    const float* __restrict__ Wo1,  const float* __restrict__ bo1,
    const float* __restrict__ Wo2,  const float* __restrict__ bo2,
    float* __restrict__ out)
{
    extern __shared__ char dynsm[];
    const uint32_t sb = cvta_s(dynsm);
    float* smf = reinterpret_cast<float*>(dynsm);
    const int tid = threadIdx.x;
    const int u = blockIdx.x;
    unsigned epoch = g_epoch_base;
    uint32_t committed[3] = {0u, 0u, 0u}, waited[3] = {0u, 0u, 0u};
    uint32_t tmem = 0;

#if HAS_TCGEN05
    if (tid < 32) {
        asm volatile(
            "tcgen05.alloc.cta_group::1.sync.aligned.shared::cta.b32 [%0], %1;"
            :: "r"(sb), "r"(128u) : "memory");
        asm volatile("tcgen05.relinquish_alloc_permit.cta_group::1.sync.aligned;");
    }
    if (tid == 0) {
        asm volatile("mbarrier.init.shared.b64 [%0], 1;" :: "r"(sb + 8) : "memory");
        asm volatile("mbarrier.init.shared.b64 [%0], 1;" :: "r"(sb + 16) : "memory");
        asm volatile("mbarrier.init.shared.b64 [%0], 1;" :: "r"(sb + 24) : "memory");
    }
    __syncthreads();
    asm volatile("ld.shared.b32 %0, [%1];" : "=r"(tmem) : "r"(sb));
#endif

    const int n4 = BB * HH / 4;

    for (int i = u * NTH + tid; i < BB * HH; i += NCTA * NTH) {
        bufH1[i] = 0.f; bufH2[i] = 0.f; g_u[i] = 1.f;
    }
    gsync(epoch, u, tid);

    for (int t = 0; t <= TT; t++) {
        // ===== phase 1: GEMMs on h1(t-1), h2(t-1), x(t) =====
        if (u < 48 && t < TT) {
            // T1: h1pre = x(t)@Wih1^T + h1@Whh1^T  (34 chunks; splitc=2)
            int jt = u / 6, s = u % 6;
            run_unit<128>(cT1[s], cT1[s + 1], 2,
                     x + (size_t)t * 64, TT * II, bufH1, HH,
                     Wih1 + (size_t)jt * 128 * II, II,
                     Whh1 + (size_t)jt * 128 * HH, HH,
                     sb, smf, tmem,
                     pH1 + (size_t)s * BB * HH + jt * 128, HH,
                     tid, committed, waited);
        } else if (u < 96 && t < TT) {
            // T2: h2@Wg2^T (cols 1024..2047 of Wg)
            int idx = u - 48, jt = idx / 6, s = idx % 6;
            run_unit<128>(cT2[s], cT2[s + 1], 0, nullptr, 0, bufH2, HH, nullptr, 0,
                     Wg + (size_t)jt * 128 * 2048 + 1024, 2048,
                     sb, smf, tmem,
                     pG + (size_t)s * BB * HH + jt * 128, HH,
                     tid, committed, waited);
        } else if (u < 136 && t < TT) {
            // T3: h2@Whh2^T
            int idx = u - 96, jt = idx / 5, s = idx % 5;
            run_unit<128>(cT3[s], cT3[s + 1], 0, nullptr, 0, bufH2, HH, nullptr, 0,
                     Whh2 + (size_t)jt * 128 * HH, HH,
                     sb, smf, tmem,
                     pH2 + (size_t)s * BB * HH + jt * 128, HH,
                     tid, committed, waited);
        } else if (u >= 136 && u < 144) {
            // T4: h2@Wo2^T (N=64; runs at every t incl. t==TT)
            int s = u - 136;
            run_unit<64>(s * 4, s * 4 + 4, 0, nullptr, 0, bufH2, HH, nullptr, 0,
                     Wo2, HH,
                     sb, smf, tmem,
                     pO + (size_t)s * BB * OO, OO,
                     tid, committed, waited);
        }
        gsync(epoch, u, tid);

        // ===== reduce 1: h1(t); u(t-1); out(t-1) =====
        if (t < TT) {
            for (int i4 = u * NTH + tid; i4 < n4; i4 += NCTA * NTH) {
                int j0 = (i4 << 2) & (HH - 1);
                float4 b1 = *reinterpret_cast<const float4*>(bih1 + j0);
                float4 b2 = *reinterpret_cast<const float4*>(bhh1 + j0);
                float4 s = make_float4(b1.x + b2.x, b1.y + b2.y,
                                       b1.z + b2.z, b1.w + b2.w);
                #pragma unroll
                for (int ss = 0; ss < 6; ss++) {
                    float4 p = __ldcg(&reinterpret_cast<const float4*>(pH1)[ss * n4 + i4]);
                    s.x += p.x; s.y += p.y; s.z += p.z; s.w += p.w;
                }
                reinterpret_cast<float4*>(bufH1)[i4] =
                    make_float4(tanhf(s.x), tanhf(s.y), tanhf(s.z), tanhf(s.w));
            }
        }
        if (t > 0 && t < TT) {
            for (int i4 = u * NTH + tid; i4 < n4; i4 += NCTA * NTH) {
                int j0 = (i4 << 2) & (HH - 1);
                float4 s = *reinterpret_cast<const float4*>(bg + j0);
                #pragma unroll
                for (int ss = 0; ss < 14; ss++) {
                    float4 p = __ldcg(&reinterpret_cast<const float4*>(pG)[ss * n4 + i4]);
                    s.x += p.x; s.y += p.y; s.z += p.z; s.w += p.w;
                }
                float4 r;
                r.x = 1.f / (1.f + expf(-s.x));
                r.y = 1.f / (1.f + expf(-s.y));
                r.z = 1.f / (1.f + expf(-s.z));
                r.w = 1.f / (1.f + expf(-s.w));
                reinterpret_cast<float4*>(g_u)[i4] = r;
            }
        }
        if (t > 0) {
            for (int i4 = u * NTH + tid; i4 < BB * OO / 4; i4 += NCTA * NTH) {
                int b = i4 >> 4;
                int o4 = (i4 & 15) * 4;
                float4 s1 = *reinterpret_cast<const float4*>(bo1 + o4);
                float4 s2 = *reinterpret_cast<const float4*>(bo2 + o4);
                #pragma unroll
                for (int ss = 8; ss < 16; ss++) {
                    float4 p = __ldcg(reinterpret_cast<const float4*>(
                        pO + (size_t)ss * BB * OO + b * OO + o4));
                    s1.x += p.x; s1.y += p.y; s1.z += p.z; s1.w += p.w;
                }
                #pragma unroll
                for (int ss = 0; ss < 8; ss++) {
                    float4 p = __ldcg(reinterpret_cast<const float4*>(
                        pO + (size_t)ss * BB * OO + b * OO + o4));
                    s2.x += p.x; s2.y += p.y; s2.z += p.z; s2.w += p.w;
                }
                float4 r;
                r.x = tanhf(s1.x) + tanhf(s2.x);
                r.y = tanhf(s1.y) + tanhf(s2.y);
                r.z = tanhf(s1.z) + tanhf(s2.z);
                r.w = tanhf(s1.w) + tanhf(s2.w);
                *reinterpret_cast<float4*>(
                    out + (size_t)b * TT * OO + (t - 1) * OO + o4) = r;
            }
        }
        if (t == TT) break;
        gsync(epoch, u, tid);

        // ===== phase 2: GEMMs on h1(t) =====
        if (u < 72) {
            // T5: h1@Wih2^T  (9 slices)
            int jt = u / 9, s = u % 9;
            run_unit<128>(cT5[s], cT5[s + 1], 0, nullptr, 0, bufH1, HH, nullptr, 0,
                     Wih2 + (size_t)jt * 128 * HH, HH,
                     sb, smf, tmem,
                     pH2 + (size_t)(5 + s) * BB * HH + jt * 128, HH,
                     tid, committed, waited);
        } else if (u < 136) {
            // T6: h1@Wg1^T (cols 0..1023)  (8 slices x 4)
            int idx = u - 72, jt = idx >> 3, s = idx & 7;
            run_unit<128>(s * 4, s * 4 + 4, 0, nullptr, 0, bufH1, HH, nullptr, 0,
                     Wg + (size_t)jt * 128 * 2048, 2048,
                     sb, smf, tmem,
                     pG + (size_t)(6 + s) * BB * HH + jt * 128, HH,
                     tid, committed, waited);
        } else if (u < 144) {
            // T7: h1@Wo1^T (N=64)
            int s = u - 136;
            run_unit<64>(s * 4, s * 4 + 4, 0, nullptr, 0, bufH1, HH, nullptr, 0,
                     Wo1, HH,
                     sb, smf, tmem,
                     pO + (size_t)(8 + s) * BB * OO, OO,
                     tid, committed, waited);
        }
        gsync(epoch, u, tid);

        // ===== reduce 2: h2(t) =====
        for (int i4 = u * NTH + tid; i4 < n4; i4 += NCTA * NTH) {
            int j0 = (i4 << 2) & (HH - 1);
            float4 b1 = *reinterpret_cast<const float4*>(bih2 + j0);
            float4 b2 = *reinterpret_cast<const float4*>(bhh2 + j0);
            float4 s = make_float4(b1.x + b2.x, b1.y + b2.y,
                                   b1.z + b2.z, b1.w + b2.w);
            #pragma unroll
            for (int ss = 0; ss < 14; ss++) {
                float4 p = __ldcg(&reinterpret_cast<const float4*>(pH2)[ss * n4 + i4]);
                s.x += p.x; s.y += p.y; s.z += p.z; s.w += p.w;
            }
            float4 uu = __ldcg(&reinterpret_cast<const float4*>(g_u)[i4]);
            float4 hp = __ldcg(&reinterpret_cast<const float4*>(bufH2)[i4]);
            float4 r;
            r.x = uu.x * tanhf(s.x) + (1.f - uu.x) * hp.x;
            r.y = uu.y * tanhf(s.y) + (1.f - uu.y) * hp.y;
            r.z = uu.z * tanhf(s.z) + (1.f - uu.z) * hp.z;
            r.w = uu.w * tanhf(s.w) + (1.f - uu.w) * hp.w;
            reinterpret_cast<float4*>(bufH2)[i4] = r;
        }
        gsync(epoch, u, tid);
    }

    if (u == 0 && tid == 0) g_epoch_base = epoch;

    __syncthreads();
#if HAS_TCGEN05
    if (tid < 32) {
        asm volatile("tcgen05.dealloc.cta_group::1.sync.aligned.b32 %0, %1;"
                     :: "r"(tmem), "r"(128u));
    }
#endif
}

// ---------------------------------------------------------------------------
extern "C" void kernel_launch(void* const* d_in, const int* in_sizes, int n_in,
                              void* d_out, int out_size) {
    const float* x    = (const float*)d_in[0];
    const float* Wih1 = (const float*)d_in[1];
    const float* bih1 = (const float*)d_in[2];
    const float* Whh1 = (const float*)d_in[3];
    const float* bhh1 = (const float*)d_in[4];
    const float* Wih2 = (const float*)d_in[5];
    const float* bih2 = (const float*)d_in[6];
    const float* Whh2 = (const float*)d_in[7];
    const float* bhh2 = (const float*)d_in[8];
    const float* Wg   = (const float*)d_in[9];
    const float* bg   = (const float*)d_in[10];
    const float* Wo1  = (const float*)d_in[11];
    const float* bo1  = (const float*)d_in[12];
    const float* Wo2  = (const float*)d_in[13];
    const float* bo2  = (const float*)d_in[14];
    float* out = (float*)d_out;

    cudaFuncSetAttribute(k_rnn, cudaFuncAttributeMaxDynamicSharedMemorySize,
                         SMEM_BYTES);

    k_rnn<<<NCTA, NTH, SMEM_BYTES>>>(x, Wih1, bih1, Whh1, bhh1,
                                     Wih2, bih2, Whh2, bhh2,
                                     Wg, bg, Wo1, bo1, Wo2, bo2, out);
}

// round 16
// speedup vs baseline: 1.0968x; 1.0968x over previous
#include <cuda_runtime.h>
#include <cstdint>

#define BB 128
#define TT 256
#define II 64
#define HH 1024
#define OO 64
#define NCTA 148
#define NTH 256
#define KC 32

#if defined(__CUDA_ARCH_FEAT_SM103_ALL) || defined(__CUDA_ARCH_SPECIFIC__)
#define HAS_TCGEN05 1
#else
#define HAS_TCGEN05 0
#endif

#define IDESC_TF32 0x8100910u   // F32 dtype, tf32 a/b, N=64, M=128

// smem: [0]=tmem ptr, mbars at 8,16,24,32; 4 buffers of 48KB at 1024+b*49152
// buffer: Ahi +0 (16KB), Alo +16384, Bhi +32768 (8KB), Blo +40960
#define SMEM_BYTES 197632

// ---------------- persistent device globals (zero-initialized) -------------
__device__ float xhi[BB * TT * II], xlo[BB * TT * II];   // [b][t*I+i]
__device__ float h1hi[BB * HH], h1lo[BB * HH];
__device__ float h2hi[BB * HH], h2lo[BB * HH];
__device__ float g_u[BB * HH];
__device__ float Wih1hi[HH * II],  Wih1lo[HH * II];
__device__ float Whh1hi[HH * HH],  Whh1lo[HH * HH];
__device__ float Wih2hi[HH * HH],  Wih2lo[HH * HH];
__device__ float Whh2hi[HH * HH],  Whh2lo[HH * HH];
__device__ float Wghi[HH * 2048],  Wglo[HH * 2048];
__device__ float Wo1hi[OO * HH],   Wo1lo[OO * HH];
__device__ float Wo2hi[OO * HH],   Wo2lo[OO * HH];
__device__ float pH1[3 * BB * HH];     // T1 slices
__device__ float pG [7 * BB * HH];     // 0-2: T2 (h2), 3-6: T6 (h1)
__device__ float pH2[7 * BB * HH];     // 0-2: T3 (h2), 3-6: T5 (h1)
__device__ float pO [7 * BB * OO];     // 0-2: T4 (Wo2*h2), 3-6: T7 (Wo1*h1)
__device__ volatile unsigned g_flags[NCTA * 32];
__device__ unsigned g_epoch_base;

// Kc=32 chunk-range tables
__constant__ int cT1[4] = {0, 12, 23, 34};   // T1: K=1088, splitc=2
__constant__ int cT2[4] = {0, 11, 22, 32};   // T2/T3: K=1024
__constant__ int cT4[4] = {0, 11, 21, 32};   // T4: K=1024, 3 slices

// ---------------------------------------------------------------------------
__device__ __forceinline__ void split1(float v, float &hi, float &lo) {
    hi = __uint_as_float(__float_as_uint(v) & 0xFFFFE000u);
    lo = v - hi;
}

__global__ void k_prepx(const float* __restrict__ x) {
    int i = blockIdx.x * blockDim.x + threadIdx.x;
    if (i < BB * TT * II) split1(x[i], xhi[i], xlo[i]);
}

// ALL output arrays referenced by symbol in DEVICE code (host-passing a
// __device__ symbol address is UB — the R7/R8/R15 bug).
__global__ void k_prepw_all(
    const float* __restrict__ Wih1, const float* __restrict__ Whh1,
    const float* __restrict__ Wih2, const float* __restrict__ Whh2,
    const float* __restrict__ Wg,
    const float* __restrict__ Wo1,  const float* __restrict__ Wo2)
{
    int stride = gridDim.x * blockDim.x;
    int t0 = blockIdx.x * blockDim.x + threadIdx.x;
    for (int i = t0; i < HH * II; i += stride)
        split1(Wih1[i], Wih1hi[i], Wih1lo[i]);
    for (int i = t0; i < HH * HH; i += stride)
        split1(Whh1[i], Whh1hi[i], Whh1lo[i]);
    for (int i = t0; i < HH * HH; i += stride)
        split1(Wih2[i], Wih2hi[i], Wih2lo[i]);
    for (int i = t0; i < HH * HH; i += stride)
        split1(Whh2[i], Whh2hi[i], Whh2lo[i]);
    for (int i = t0; i < HH * 2048; i += stride)
        split1(Wg[i], Wghi[i], Wglo[i]);
    for (int i = t0; i < OO * HH; i += stride)
        split1(Wo1[i], Wo1hi[i], Wo1lo[i]);
    for (int i = t0; i < OO * HH; i += stride)
        split1(Wo2[i], Wo2hi[i], Wo2lo[i]);
}

// ---------------------------------------------------------------------------
__device__ __forceinline__ uint32_t cvta_s(const void* p) {
    uint32_t a;
    asm("{ .reg .u64 t; cvta.to.shared.u64 t, %1; cvt.u32.u64 %0, t; }"
        : "=r"(a) : "l"(p));
    return a;
}

__device__ __forceinline__ bool elect1() {
    uint32_t p;
    asm volatile("{ .reg .pred p; elect.sync _|p, 0xFFFFFFFF; selp.b32 %0, 1, 0, p; }"
                 : "=r"(p));
    return p != 0;
}

__device__ __forceinline__ uint64_t sdesc(uint32_t addr) {
    return 0x4000404000010000ull | ((uint64_t)(addr >> 4) & 0x3FFF);
}

__device__ __forceinline__ void mbar_wait(uint32_t mbar, uint32_t parity) {
    asm volatile(
        "{\n\t.reg .pred P;\n\t"
        "WL%=:\n\t"
        "mbarrier.try_wait.parity.acquire.cta.shared::cta.b64 P, [%0], %1, 0x989680;\n\t"
        "@!P bra WL%=;\n\t}"
        :: "r"(mbar), "r"(parity) : "memory");
}

__device__ __forceinline__ void gsync(unsigned &epoch, int u, int tid) {
    __syncthreads();
    epoch++;
    __threadfence();
    if (tid == 0) g_flags[u * 32] = epoch;
    for (int i = tid; i < NCTA; i += NTH)
        while (g_flags[i * 32] < epoch) { }
    __syncthreads();
    __threadfence();
}

#if HAS_TCGEN05
#define LDTM32(r, a) \
    asm volatile( \
        "tcgen05.ld.sync.aligned.32x32b.x32.b32 " \
        "{%0, %1, %2, %3, %4, %5, %6, %7, " \
        " %8, %9, %10, %11, %12, %13, %14, %15, " \
        " %16, %17, %18, %19, %20, %21, %22, %23, " \
        " %24, %25, %26, %27, %28, %29, %30, %31}, [%32];" \
        : "=r"((r)[0]),  "=r"((r)[1]),  "=r"((r)[2]),  "=r"((r)[3]), \
          "=r"((r)[4]),  "=r"((r)[5]),  "=r"((r)[6]),  "=r"((r)[7]), \
          "=r"((r)[8]),  "=r"((r)[9]),  "=r"((r)[10]), "=r"((r)[11]), \
          "=r"((r)[12]), "=r"((r)[13]), "=r"((r)[14]), "=r"((r)[15]), \
          "=r"((r)[16]), "=r"((r)[17]), "=r"((r)[18]), "=r"((r)[19]), \
          "=r"((r)[20]), "=r"((r)[21]), "=r"((r)[22]), "=r"((r)[23]), \
          "=r"((r)[24]), "=r"((r)[25]), "=r"((r)[26]), "=r"((r)[27]), \
          "=r"((r)[28]), "=r"((r)[29]), "=r"((r)[30]), "=r"((r)[31]) \
        : "r"(a))

__device__ __forceinline__ void mma_tf32(uint32_t tmem, uint64_t a, uint64_t b,
                                         uint32_t en) {
    asm volatile(
        "{\n\t.reg .pred p;\n\t"
        "setp.ne.u32 p, %4, 0;\n\t"
        "tcgen05.mma.cta_group::1.kind::tf32 [%0], %1, %2, %3, "
        "{%5, %5, %5, %5}, p;\n\t}"
        :: "r"(tmem), "l"(a), "l"(b), "r"(IDESC_TF32), "r"(en), "r"(0u)
        : "memory");
}
#endif

// ---------------------------------------------------------------------------
// Issue one chunk's cp.asyncs: Ahi/Alo 128x32, Bhi/Blo 64x32, SW128 tiles.
__device__ __forceinline__ void cp_chunk(
    int c, int splitc,
    const float* __restrict__ Ah0, const float* __restrict__ Al0, int lda0,
    const float* __restrict__ Ah1, const float* __restrict__ Al1, int lda1,
    const float* __restrict__ Bh0, const float* __restrict__ Bl0, int ldb0,
    const float* __restrict__ Bh1, const float* __restrict__ Bl1, int ldb1,
    uint32_t sbuf, int tid)
{
    const float *Ah, *Al, *Bh, *Bl; int la, lb; size_t ko;
    if (c < splitc) { Ah = Ah0; Al = Al0; la = lda0; Bh = Bh0; Bl = Bl0;
                      lb = ldb0; ko = (size_t)c * KC; }
    else            { Ah = Ah1; Al = Al1; la = lda1; Bh = Bh1; Bl = Bl1;
                      lb = ldb1; ko = (size_t)(c - splitc) * KC; }
    const int F4R = KC / 4;                       // float4 per row = 8
    #pragma unroll
    for (int r = 0; r < 128 * F4R / NTH; r++) {   // A: 4 per thread
        int i = tid + r * NTH;
        int rr = i / F4R, c4 = i % F4R;
        int bo = ((rr >> 3) << 10) | ((rr & 7) << 7) | (c4 << 4);
        uint32_t sw = bo ^ ((bo >> 3) & 0x70);
        size_t go = (size_t)rr * la + ko + c4 * 4;
        asm volatile("cp.async.cg.shared.global [%0], [%1], 16;"
                     :: "r"(sbuf + sw), "l"(Ah + go));
        asm volatile("cp.async.cg.shared.global [%0], [%1], 16;"
                     :: "r"(sbuf + 16384 + sw), "l"(Al + go));
    }
    #pragma unroll
    for (int r = 0; r < 64 * F4R / NTH; r++) {    // B: 2 per thread
        int i = tid + r * NTH;
        int rr = i / F4R, c4 = i % F4R;
        int bo = ((rr >> 3) << 10) | ((rr & 7) << 7) | (c4 << 4);
        uint32_t sw = bo ^ ((bo >> 3) & 0x70);
        size_t go = (size_t)rr * lb + ko + c4 * 4;
        asm volatile("cp.async.cg.shared.global [%0], [%1], 16;"
                     :: "r"(sbuf + 32768 + sw), "l"(Bh + go));
        asm volatile("cp.async.cg.shared.global [%0], [%1], 16;"
                     :: "r"(sbuf + 40960 + sw), "l"(Bl + go));
    }
}

// ---------------------------------------------------------------------------
// Split-K unit: D[b=128][64] += A[128 x KC-chunks] @ B[64 x ...]^T, 3xTF32.
// 4 smem buffers; cp groups depth-2 (wait_group 1); MMA depth-2 (mbars).
__device__ __forceinline__ void run_unit(
    int c0, int c1, int splitc,
    const float* __restrict__ Ah0, const float* __restrict__ Al0, int lda0,
    const float* __restrict__ Ah1, const float* __restrict__ Al1, int lda1,
    const float* __restrict__ Bh0, const float* __restrict__ Bl0, int ldb0,
    const float* __restrict__ Bh1, const float* __restrict__ Bl1, int ldb1,
    uint32_t sb, uint32_t tmem, float* __restrict__ dst, int ldd,
    int tid, uint32_t* committed, uint32_t* waited)
{
#if HAS_TCGEN05
    const int n = c1 - c0;
    for (int k = 0; k < 2 && k < n; k++) {        // prologue: stage 2 chunks
        int bn = k & 3;
        if (committed[bn] > waited[bn]) {
            mbar_wait(sb + 8 + bn * 8, waited[bn] & 1);
            waited[bn]++;
        }
        cp_chunk(c0 + k, splitc, Ah0, Al0, lda0, Ah1, Al1, lda1,
                 Bh0, Bl0, ldb0, Bh1, Bl1, ldb1,
                 sb + 1024 + bn * 49152, tid);
        asm volatile("cp.async.commit_group;" ::: "memory");
    }
    for (int c = c0; c < c1; c++) {
        const int b = (c - c0) & 3;
        if (c + 1 < c1) asm volatile("cp.async.wait_group 1;" ::: "memory");
        else            asm volatile("cp.async.wait_group 0;" ::: "memory");
        asm volatile("fence.proxy.async.shared::cta;" ::: "memory");
        __syncthreads();

        const uint32_t sA = sb + 1024 + b * 49152;
        if (tid < 32 && elect1()) {
            uint64_t dahi = sdesc(sA),          dalo = sdesc(sA + 16384);
            uint64_t dbhi = sdesc(sA + 32768),  dblo = sdesc(sA + 40960);
            #pragma unroll
            for (int s = 0; s < KC / 8; s++) {
                uint64_t o = (uint64_t)(s << 1);
                mma_tf32(tmem, dahi + o, dbhi + o, (c > c0 || s > 0) ? 1u : 0u);
                mma_tf32(tmem, dahi + o, dblo + o, 1u);
                mma_tf32(tmem, dalo + o, dbhi + o, 1u);
            }
            asm volatile(
                "tcgen05.commit.cta_group::1.mbarrier::arrive::one.shared::cluster.b64 [%0];"
                :: "r"(sb + 8 + b * 8) : "memory");
        }
        committed[b]++;

        int f = c + 2;                            // stage chunk c+2
        if (f < c1) {
            int bn = (f - c0) & 3;
            if (committed[bn] > waited[bn]) {
                mbar_wait(sb + 8 + bn * 8, waited[bn] & 1);
                waited[bn]++;
            }
            cp_chunk(f, splitc, Ah0, Al0, lda0, Ah1, Al1, lda1,
                     Bh0, Bl0, ldb0, Bh1, Bl1, ldb1,
                     sb + 1024 + bn * 49152, tid);
            asm volatile("cp.async.commit_group;" ::: "memory");
        }
    }
    #pragma unroll
    for (int b = 0; b < 4; b++) {                 // drain MMAs
        if (committed[b] > waited[b]) {
            mbar_wait(sb + 8 + b * 8, waited[b] & 1);
            waited[b]++;
        }
    }
    asm volatile("tcgen05.fence::after_thread_sync;" ::: "memory");

    if (tid < 128) {
        uint32_t d0[32], d1[32];
        LDTM32(d0, tmem);
        LDTM32(d1, tmem + 32);
        asm volatile("tcgen05.wait::ld.sync.aligned;" ::: "memory");
        asm volatile("tcgen05.fence::before_thread_sync;" ::: "memory");
        float* drow = dst + (size_t)tid * ldd;
        #pragma unroll
        for (int c4 = 0; c4 < 8; c4++) {
            *reinterpret_cast<float4*>(drow + c4 * 4) = make_float4(
                __uint_as_float(d0[c4 * 4 + 0]), __uint_as_float(d0[c4 * 4 + 1]),
                __uint_as_float(d0[c4 * 4 + 2]), __uint_as_float(d0[c4 * 4 + 3]));
            *reinterpret_cast<float4*>(drow + 32 + c4 * 4) = make_float4(
                __uint_as_float(d1[c4 * 4 + 0]), __uint_as_float(d1[c4 * 4 + 1]),
                __uint_as_float(d1[c4 * 4 + 2]), __uint_as_float(d1[c4 * 4 + 3]));
        }
    }
    __syncthreads();
#else
    // ---- SIMT fallback (base-arch pass only; never selected at runtime) ----
    (void)sb; (void)tmem; (void)committed; (void)waited;
    if (tid < 128) {
        float acc[64];
        #pragma unroll
        for (int j = 0; j < 64; j++) acc[j] = 0.f;
        for (int c = c0; c < c1; c++) {
            const float *Ah, *Al, *Bh, *Bl; int la, lb; size_t ko;
            if (c < splitc) { Ah = Ah0; Al = Al0; la = lda0; Bh = Bh0; Bl = Bl0;
                              lb = ldb0; ko = (size_t)c * KC; }
            else            { Ah = Ah1; Al = Al1; la = lda1; Bh = Bh1; Bl = Bl1;
                              lb = ldb1; ko = (size_t)(c - splitc) * KC; }
            for (int k = 0; k < KC; k++) {
                float a = Ah[(size_t)tid * la + ko + k] + Al[(size_t)tid * la + ko + k];
                for (int j = 0; j < 64; j++)
                    acc[j] += a * (Bh[(size_t)j * lb + ko + k] + Bl[(size_t)j * lb + ko + k]);
            }
        }
        float* drow = dst + (size_t)tid * ldd;
        for (int j = 0; j < 64; j++) drow[j] = acc[j];
    }
    __syncthreads();
#endif
}

// ---------------------------------------------------------------------------
__global__ void __launch_bounds__(NTH, 1) k_rnn(
    const float* __restrict__ bih1, const float* __restrict__ bhh1,
    const float* __restrict__ bih2, const float* __restrict__ bhh2,
    const float* __restrict__ bg,
    const float* __restrict__ bo1, const float* __restrict__ bo2,
    float* __restrict__ out)
{
    extern __shared__ char dynsm[];
    const uint32_t sb = cvta_s(dynsm);
    const int tid = threadIdx.x;
    const int u = blockIdx.x;
    unsigned epoch = g_epoch_base;
    uint32_t committed[4] = {0u, 0u, 0u, 0u}, waited[4] = {0u, 0u, 0u, 0u};
    uint32_t tmem = 0;

#if HAS_TCGEN05
    if (tid < 32) {
        asm volatile(
            "tcgen05.alloc.cta_group::1.sync.aligned.shared::cta.b32 [%0], %1;"
            :: "r"(sb), "r"(64u) : "memory");
        asm volatile("tcgen05.relinquish_alloc_permit.cta_group::1.sync.aligned;");
    }
    if (tid == 0) {
        #pragma unroll
        for (int b = 0; b < 4; b++)
            asm volatile("mbarrier.init.shared.b64 [%0], 1;"
                         :: "r"(sb + 8 + b * 8) : "memory");
    }
    __syncthreads();
    asm volatile("ld.shared.b32 %0, [%1];" : "=r"(tmem) : "r"(sb));
#endif

    const int n4 = BB * HH / 4;

    for (int i = u * NTH + tid; i < BB * HH; i += NCTA * NTH) {
        h1hi[i] = 0.f; h1lo[i] = 0.f;
        h2hi[i] = 0.f; h2lo[i] = 0.f;
        g_u[i] = 1.f;
    }
    gsync(epoch, u, tid);

    for (int t = 0; t <= TT; t++) {
        // ===== phase 1: GEMMs on h1(t-1), h2(t-1), x(t) =====
        if (u < 48 && t < TT) {
            int jt = u / 3, s = u % 3;
            run_unit(cT1[s], cT1[s + 1], 2,
                     xhi + (size_t)t * 64, xlo + (size_t)t * 64, TT * II,
                     h1hi, h1lo, HH,
                     Wih1hi + (size_t)jt * 64 * II, Wih1lo + (size_t)jt * 64 * II, II,
                     Whh1hi + (size_t)jt * 64 * HH, Whh1lo + (size_t)jt * 64 * HH, HH,
                     sb, tmem,
                     pH1 + (size_t)s * BB * HH + jt * 64, HH,
                     tid, committed, waited);
        } else if (u < 96 && t < TT) {
            int idx = u - 48, jt = idx / 3, s = idx % 3;
            run_unit(cT2[s], cT2[s + 1], 0,
                     nullptr, nullptr, 0, h2hi, h2lo, HH,
                     nullptr, nullptr, 0,
                     Wghi + (size_t)jt * 64 * 2048 + 1024,
                     Wglo + (size_t)jt * 64 * 2048 + 1024, 2048,
                     sb, tmem,
                     pG + (size_t)s * BB * HH + jt * 64, HH,
                     tid, committed, waited);
        } else if (u < 144 && t < TT) {
            int idx = u - 96, jt = idx / 3, s = idx % 3;
            run_unit(cT2[s], cT2[s + 1], 0,
                     nullptr, nullptr, 0, h2hi, h2lo, HH,
                     nullptr, nullptr, 0,
                     Whh2hi + (size_t)jt * 64 * HH, Whh2lo + (size_t)jt * 64 * HH, HH,
                     sb, tmem,
                     pH2 + (size_t)s * BB * HH + jt * 64, HH,
                     tid, committed, waited);
        } else if (u >= 144 && u < 147) {
            int s = u - 144;
            run_unit(cT4[s], cT4[s + 1], 0,
                     nullptr, nullptr, 0, h2hi, h2lo, HH,
                     nullptr, nullptr, 0, Wo2hi, Wo2lo, HH,
                     sb, tmem,
                     pO + (size_t)s * BB * OO, OO,
                     tid, committed, waited);
        }
        gsync(epoch, u, tid);

        // ===== reduce 1: h1(t) split; u(t-1); out(t-1) =====
        if (t < TT) {
            for (int i4 = u * NTH + tid; i4 < n4; i4 += NCTA * NTH) {
                int j0 = (i4 << 2) & (HH - 1);
                float4 b1 = *reinterpret_cast<const float4*>(bih1 + j0);
                float4 b2 = *reinterpret_cast<const float4*>(bhh1 + j0);
                float4 s = make_float4(b1.x + b2.x, b1.y + b2.y,
                                       b1.z + b2.z, b1.w + b2.w);
                #pragma unroll
                for (int ss = 0; ss < 3; ss++) {
                    float4 p = __ldcg(&reinterpret_cast<const float4*>(pH1)[ss * n4 + i4]);
                    s.x += p.x; s.y += p.y; s.z += p.z; s.w += p.w;
                }
                float4 v = make_float4(tanhf(s.x), tanhf(s.y), tanhf(s.z), tanhf(s.w));
                float4 hi, lo;
                split1(v.x, hi.x, lo.x); split1(v.y, hi.y, lo.y);
                split1(v.z, hi.z, lo.z); split1(v.w, hi.w, lo.w);
                reinterpret_cast<float4*>(h1hi)[i4] = hi;
                reinterpret_cast<float4*>(h1lo)[i4] = lo;
            }
        }
        if (t > 0 && t < TT) {
            for (int i4 = u * NTH + tid; i4 < n4; i4 += NCTA * NTH) {
                int j0 = (i4 << 2) & (HH - 1);
                float4 s = *reinterpret_cast<const float4*>(bg + j0);
                #pragma unroll
                for (int ss = 0; ss < 7; ss++) {
                    float4 p = __ldcg(&reinterpret_cast<const float4*>(pG)[ss * n4 + i4]);
                    s.x += p.x; s.y += p.y; s.z += p.z; s.w += p.w;
                }
                float4 r;
                r.x = 1.f / (1.f + expf(-s.x));
                r.y = 1.f / (1.f + expf(-s.y));
                r.z = 1.f / (1.f + expf(-s.z));
                r.w = 1.f / (1.f + expf(-s.w));
                reinterpret_cast<float4*>(g_u)[i4] = r;
            }
        }
        if (t > 0) {
            for (int i4 = u * NTH + tid; i4 < BB * OO / 4; i4 += NCTA * NTH) {
                int b = i4 >> 4;
                int o4 = (i4 & 15) * 4;
                float4 s1 = *reinterpret_cast<const float4*>(bo1 + o4);
                float4 s2 = *reinterpret_cast<const float4*>(bo2 + o4);
                #pragma unroll
                for (int ss = 3; ss < 7; ss++) {
                    float4 p = __ldcg(reinterpret_cast<const float4*>(
                        pO + (size_t)ss * BB * OO + b * OO + o4));
                    s1.x += p.x; s1.y += p.y; s1.z += p.z; s1.w += p.w;
                }
                #pragma unroll
                for (int ss = 0; ss < 3; ss++) {
                    float4 p = __ldcg(reinterpret_cast<const float4*>(
                        pO + (size_t)ss * BB * OO + b * OO + o4));
                    s2.x += p.x; s2.y += p.y; s2.z += p.z; s2.w += p.w;
                }
                float4 r;
                r.x = tanhf(s1.x) + tanhf(s2.x);
                r.y = tanhf(s1.y) + tanhf(s2.y);
                r.z = tanhf(s1.z) + tanhf(s2.z);
                r.w = tanhf(s1.w) + tanhf(s2.w);
                *reinterpret_cast<float4*>(
                    out + (size_t)b * TT * OO + (t - 1) * OO + o4) = r;
            }
        }
        if (t == TT) break;
        gsync(epoch, u, tid);

        // ===== phase 2: GEMMs on h1(t) =====
        if (u < 64) {
            int jt = u >> 2, s = u & 3;
            run_unit(s * 8, s * 8 + 8, 0,
                     nullptr, nullptr, 0, h1hi, h1lo, HH,
                     nullptr, nullptr, 0,
                     Wih2hi + (size_t)jt * 64 * HH, Wih2lo + (size_t)jt * 64 * HH, HH,
                     sb, tmem,
                     pH2 + (size_t)(3 + s) * BB * HH + jt * 64, HH,
                     tid, committed, waited);
        } else if (u < 128) {
            int idx = u - 64, jt = idx >> 2, s = idx & 3;
            run_unit(s * 8, s * 8 + 8, 0,
                     nullptr, nullptr, 0, h1hi, h1lo, HH,
                     nullptr, nullptr, 0,
                     Wghi + (size_t)jt * 64 * 2048, Wglo + (size_t)jt * 64 * 2048, 2048,
                     sb, tmem,
                     pG + (size_t)(3 + s) * BB * HH + jt * 64, HH,
                     tid, committed, waited);
        } else if (u < 132) {
            int s = u - 128;
            run_unit(s * 8, s * 8 + 8, 0,
                     nullptr, nullptr, 0, h1hi, h1lo, HH,
                     nullptr, nullptr, 0, Wo1hi, Wo1lo, HH,
                     sb, tmem,
                     pO + (size_t)(3 + s) * BB * OO, OO,
                     tid, committed, waited);
        }
        gsync(epoch, u, tid);

        // ===== reduce 2: h2(t) =====
        for (int i4 = u * NTH + tid; i4 < n4; i4 += NCTA * NTH) {
            int j0 = (i4 << 2) & (HH - 1);
            float4 b1 = *reinterpret_cast<const float4*>(bih2 + j0);
            float4 b2 = *reinterpret_cast<const float4*>(bhh2 + j0);
            float4 s = make_float4(b1.x + b2.x, b1.y + b2.y,
                                   b1.z + b2.z, b1.w + b2.w);
            #pragma unroll
            for (int ss = 0; ss < 7; ss++) {
                float4 p = __ldcg(&reinterpret_cast<const float4*>(pH2)[ss * n4 + i4]);
                s.x += p.x; s.y += p.y; s.z += p.z; s.w += p.w;
            }
            float4 uu = __ldcg(&reinterpret_cast<const float4*>(g_u)[i4]);
            float4 ph = __ldcg(&reinterpret_cast<const float4*>(h2hi)[i4]);
            float4 pl = __ldcg(&reinterpret_cast<const float4*>(h2lo)[i4]);
            float4 v;
            v.x = uu.x * tanhf(s.x) + (1.f - uu.x) * (ph.x + pl.x);
            v.y = uu.y * tanhf(s.y) + (1.f - uu.y) * (ph.y + pl.y);
            v.z = uu.z * tanhf(s.z) + (1.f - uu.z) * (ph.z + pl.z);
            v.w = uu.w * tanhf(s.w) + (1.f - uu.w) * (ph.w + pl.w);
            float4 hi, lo;
            split1(v.x, hi.x, lo.x); split1(v.y, hi.y, lo.y);
            split1(v.z, hi.z, lo.z); split1(v.w, hi.w, lo.w);
            reinterpret_cast<float4*>(h2hi)[i4] = hi;
            reinterpret_cast<float4*>(h2lo)[i4] = lo;
        }
        gsync(epoch, u, tid);
    }

    if (u == 0 && tid == 0) g_epoch_base = epoch;

    __syncthreads();
#if HAS_TCGEN05
    if (tid < 32) {
        asm volatile("tcgen05.dealloc.cta_group::1.sync.aligned.b32 %0, %1;"
                     :: "r"(tmem), "r"(64u));
    }
#endif
}

// ---------------------------------------------------------------------------
extern "C" void kernel_launch(void* const* d_in, const int* in_sizes, int n_in,
                              void* d_out, int out_size) {
    const float* x    = (const float*)d_in[0];
    const float* Wih1 = (const float*)d_in[1];
    const float* bih1 = (const float*)d_in[2];
    const float* Whh1 = (const float*)d_in[3];
    const float* bhh1 = (const float*)d_in[4];
    const float* Wih2 = (const float*)d_in[5];
    const float* bih2 = (const float*)d_in[6];
    const float* Whh2 = (const float*)d_in[7];
    const float* bhh2 = (const float*)d_in[8];
    const float* Wg   = (const float*)d_in[9];
    const float* bg   = (const float*)d_in[10];
    const float* Wo1  = (const float*)d_in[11];
    const float* bo1  = (const float*)d_in[12];
    const float* Wo2  = (const float*)d_in[13];
    const float* bo2  = (const float*)d_in[14];
    float* out = (float*)d_out;

    cudaFuncSetAttribute(k_rnn, cudaFuncAttributeMaxDynamicSharedMemorySize,
                         SMEM_BYTES);

    k_prepx<<<(BB * TT * II + 255) / 256, 256>>>(x);
    k_prepw_all<<<1024, 256>>>(Wih1, Whh1, Wih2, Whh2, Wg, Wo1, Wo2);
    k_rnn<<<NCTA, NTH, SMEM_BYTES>>>(bih1, bhh1, bih2, bhh2, bg, bo1, bo2, out);
}

// round 17
// speedup vs baseline: 1.3857x; 1.2634x over previous
#include <cuda_runtime.h>
#include <cuda_bf16.h>
#include <cstdint>

#define BB 128
#define TT 256
#define II 64
#define HH 1024
#define OO 64
#define NCTA 148
#define NTH 256
#define KC 64

#if defined(__CUDA_ARCH_FEAT_SM103_ALL) || defined(__CUDA_ARCH_SPECIFIC__)
#define HAS_TCGEN05 1
#else
#define HAS_TCGEN05 0
#endif

// idesc bf16: dtype=F32(1<<4), atype=BF16(1<<7), btype=BF16(1<<10), N/8=8<<17, M/16=8<<24
#define IDESC_BF16 0x8100490u

// smem: [0]=tmem ptr, mbars at 8,16,24,32; 4 buffers of 48KB at 1024+b*49152
// buffer: Ahi +0 (16KB), Alo +16384 (16KB), Bhi +32768 (8KB), Blo +40960 (8KB)
#define SMEM_BYTES 197632

typedef __nv_bfloat16 bf16;

// ---------------- persistent device globals (zero-initialized) -------------
__device__ bf16 xhi[BB * TT * II], xlo[BB * TT * II];   // [b][t*I+i]
__device__ bf16 h1hi[BB * HH], h1lo[BB * HH];
__device__ bf16 h2hi[BB * HH], h2lo[BB * HH];
__device__ float g_u[BB * HH];
__device__ bf16 Wih1hi[HH * II],  Wih1lo[HH * II];
__device__ bf16 Whh1hi[HH * HH],  Whh1lo[HH * HH];
__device__ bf16 Wih2hi[HH * HH],  Wih2lo[HH * HH];
__device__ bf16 Whh2hi[HH * HH],  Whh2lo[HH * HH];
__device__ bf16 Wghi[HH * 2048],  Wglo[HH * 2048];
__device__ bf16 Wo1hi[OO * HH],   Wo1lo[OO * HH];
__device__ bf16 Wo2hi[OO * HH],   Wo2lo[OO * HH];
__device__ float pH1[3 * BB * HH];     // T1 slices
__device__ float pG [7 * BB * HH];     // 0-2: T2 (h2), 3-6: T6 (h1)
__device__ float pH2[7 * BB * HH];     // 0-2: T3 (h2), 3-6: T5 (h1)
__device__ float pO [7 * BB * OO];     // 0-2: T4 (Wo2*h2), 3-6: T7 (Wo1*h1)
__device__ volatile unsigned g_flags[NCTA * 32];
__device__ unsigned g_epoch_base;

// Kc=64 chunk-range tables
__constant__ int cT1[4] = {0, 6, 11, 17};   // T1: K=1088 (splitc=1)
__constant__ int cT2[4] = {0, 6, 11, 16};   // T2/T3: K=1024
__constant__ int cT4[4] = {0, 6, 11, 16};   // T4

// ---------------------------------------------------------------------------
// bf16 compensated split: hi = bf16(v); r = v - hi (exact fp32); lo = bf16(r)
__device__ __forceinline__ void splitbf(float v, bf16 &hi, bf16 &lo) {
    hi = __float2bfloat16(v);
    lo = __float2bfloat16(v - __bfloat162float(hi));
}

__device__ __forceinline__ uint32_t pack2(float a, float b) {
    __nv_bfloat162 t = __floats2bfloat162_rn(a, b);  // (a, b) -> lo, hi halves
    return *reinterpret_cast<uint32_t*>(&t);
}

__global__ void k_prepx(const float* __restrict__ x) {
    int i = blockIdx.x * blockDim.x + threadIdx.x;
    if (i < BB * TT * II) splitbf(x[i], xhi[i], xlo[i]);
}

// outputs referenced by symbol in device code only (host-passing is UB)
__global__ void k_prepw_all(
    const float* __restrict__ Wih1, const float* __restrict__ Whh1,
    const float* __restrict__ Wih2, const float* __restrict__ Whh2,
    const float* __restrict__ Wg,
    const float* __restrict__ Wo1,  const float* __restrict__ Wo2)
{
    int stride = gridDim.x * blockDim.x;
    int t0 = blockIdx.x * blockDim.x + threadIdx.x;
    for (int i = t0; i < HH * II; i += stride)  splitbf(Wih1[i], Wih1hi[i], Wih1lo[i]);
    for (int i = t0; i < HH * HH; i += stride)  splitbf(Whh1[i], Whh1hi[i], Whh1lo[i]);
    for (int i = t0; i < HH * HH; i += stride)  splitbf(Wih2[i], Wih2hi[i], Wih2lo[i]);
    for (int i = t0; i < HH * HH; i += stride)  splitbf(Whh2[i], Whh2hi[i], Whh2lo[i]);
    for (int i = t0; i < HH * 2048; i += stride) splitbf(Wg[i], Wghi[i], Wglo[i]);
    for (int i = t0; i < OO * HH; i += stride)  splitbf(Wo1[i], Wo1hi[i], Wo1lo[i]);
    for (int i = t0; i < OO * HH; i += stride)  splitbf(Wo2[i], Wo2hi[i], Wo2lo[i]);
}

// ---------------------------------------------------------------------------
__device__ __forceinline__ uint32_t cvta_s(const void* p) {
    uint32_t a;
    asm("{ .reg .u64 t; cvta.to.shared.u64 t, %1; cvt.u32.u64 %0, t; }"
        : "=r"(a) : "l"(p));
    return a;
}

__device__ __forceinline__ bool elect1() {
    uint32_t p;
    asm volatile("{ .reg .pred p; elect.sync _|p, 0xFFFFFFFF; selp.b32 %0, 1, 0, p; }"
                 : "=r"(p));
    return p != 0;
}

__device__ __forceinline__ uint64_t sdesc(uint32_t addr) {
    return 0x4000404000010000ull | ((uint64_t)(addr >> 4) & 0x3FFF);
}

__device__ __forceinline__ void mbar_wait(uint32_t mbar, uint32_t parity) {
    asm volatile(
        "{\n\t.reg .pred P;\n\t"
        "WL%=:\n\t"
        "mbarrier.try_wait.parity.acquire.cta.shared::cta.b64 P, [%0], %1, 0x989680;\n\t"
        "@!P bra WL%=;\n\t}"
        :: "r"(mbar), "r"(parity) : "memory");
}

__device__ __forceinline__ void gsync(unsigned &epoch, int u, int tid) {
    __syncthreads();
    epoch++;
    __threadfence();
    if (tid == 0) g_flags[u * 32] = epoch;
    for (int i = tid; i < NCTA; i += NTH)
        while (g_flags[i * 32] < epoch) { }
    __syncthreads();
    __threadfence();
}

#if HAS_TCGEN05
#define LDTM32(r, a) \
    asm volatile( \
        "tcgen05.ld.sync.aligned.32x32b.x32.b32 " \
        "{%0, %1, %2, %3, %4, %5, %6, %7, " \
        " %8, %9, %10, %11, %12, %13, %14, %15, " \
        " %16, %17, %18, %19, %20, %21, %22, %23, " \
        " %24, %25, %26, %27, %28, %29, %30, %31}, [%32];" \
        : "=r"((r)[0]),  "=r"((r)[1]),  "=r"((r)[2]),  "=r"((r)[3]), \
          "=r"((r)[4]),  "=r"((r)[5]),  "=r"((r)[6]),  "=r"((r)[7]), \
          "=r"((r)[8]),  "=r"((r)[9]),  "=r"((r)[10]), "=r"((r)[11]), \
          "=r"((r)[12]), "=r"((r)[13]), "=r"((r)[14]), "=r"((r)[15]), \
          "=r"((r)[16]), "=r"((r)[17]), "=r"((r)[18]), "=r"((r)[19]), \
          "=r"((r)[20]), "=r"((r)[21]), "=r"((r)[22]), "=r"((r)[23]), \
          "=r"((r)[24]), "=r"((r)[25]), "=r"((r)[26]), "=r"((r)[27]), \
          "=r"((r)[28]), "=r"((r)[29]), "=r"((r)[30]), "=r"((r)[31]) \
        : "r"(a))

__device__ __forceinline__ void mma_bf16(uint32_t tmem, uint64_t a, uint64_t b,
                                         uint32_t en) {
    asm volatile(
        "{\n\t.reg .pred p;\n\t"
        "setp.ne.u32 p, %4, 0;\n\t"
        "tcgen05.mma.cta_group::1.kind::f16 [%0], %1, %2, %3, "
        "{%5, %5, %5, %5}, p;\n\t}"
        :: "r"(tmem), "l"(a), "l"(b), "r"(IDESC_BF16), "r"(en), "r"(0u)
        : "memory");
}
#endif

// ---------------------------------------------------------------------------
// One chunk's cp.asyncs: Ahi/Alo 128 x 64 bf16 (128B rows), Bhi/Blo 64 x 64.
// Granule = 16B = 8 bf16; SW128 atom geometry identical to prior rounds.
__device__ __forceinline__ void cp_chunk(
    int c, int splitc,
    const bf16* __restrict__ Ah0, const bf16* __restrict__ Al0, int lda0,
    const bf16* __restrict__ Ah1, const bf16* __restrict__ Al1, int lda1,
    const bf16* __restrict__ Bh0, const bf16* __restrict__ Bl0, int ldb0,
    const bf16* __restrict__ Bh1, const bf16* __restrict__ Bl1, int ldb1,
    uint32_t sbuf, int tid)
{
    const bf16 *Ah, *Al, *Bh, *Bl; int la, lb; size_t ko;
    if (c < splitc) { Ah = Ah0; Al = Al0; la = lda0; Bh = Bh0; Bl = Bl0;
                      lb = ldb0; ko = (size_t)c * KC; }
    else            { Ah = Ah1; Al = Al1; la = lda1; Bh = Bh1; Bl = Bl1;
                      lb = ldb1; ko = (size_t)(c - splitc) * KC; }
    const int G = KC / 8;                          // 16B granules per row = 8
    #pragma unroll
    for (int r = 0; r < 128 * G / NTH; r++) {      // A: 4 per thread
        int i = tid + r * NTH;
        int rr = i / G, c8 = i % G;
        int bo = ((rr >> 3) << 10) | ((rr & 7) << 7) | (c8 << 4);
        uint32_t sw = bo ^ ((bo >> 3) & 0x70);
        size_t go = (size_t)rr * la + ko + c8 * 8;
        asm volatile("cp.async.cg.shared.global [%0], [%1], 16;"
                     :: "r"(sbuf + sw), "l"(Ah + go));
        asm volatile("cp.async.cg.shared.global [%0], [%1], 16;"
                     :: "r"(sbuf + 16384 + sw), "l"(Al + go));
    }
    #pragma unroll
    for (int r = 0; r < 64 * G / NTH; r++) {       // B: 2 per thread
        int i = tid + r * NTH;
        int rr = i / G, c8 = i % G;
        int bo = ((rr >> 3) << 10) | ((rr & 7) << 7) | (c8 << 4);
        uint32_t sw = bo ^ ((bo >> 3) & 0x70);
        size_t go = (size_t)rr * lb + ko + c8 * 8;
        asm volatile("cp.async.cg.shared.global [%0], [%1], 16;"
                     :: "r"(sbuf + 32768 + sw), "l"(Bh + go));
        asm volatile("cp.async.cg.shared.global [%0], [%1], 16;"
                     :: "r"(sbuf + 40960 + sw), "l"(Bl + go));
    }
}

// ---------------------------------------------------------------------------
// Split-K unit: D[b=128][64] += A[128 x KC-chunks] @ B[64 x ...]^T, 3xBF16.
// 4 smem buffers; cp groups depth-2 (wait_group 1); MMA depth-2 (mbars).
__device__ __forceinline__ void run_unit(
    int c0, int c1, int splitc,
    const bf16* __restrict__ Ah0, const bf16* __restrict__ Al0, int lda0,
    const bf16* __restrict__ Ah1, const bf16* __restrict__ Al1, int lda1,
    const bf16* __restrict__ Bh0, const bf16* __restrict__ Bl0, int ldb0,
    const bf16* __restrict__ Bh1, const bf16* __restrict__ Bl1, int ldb1,
    uint32_t sb, uint32_t tmem, float* __restrict__ dst, int ldd,
    int tid, uint32_t* committed, uint32_t* waited)
{
#if HAS_TCGEN05
    const int n = c1 - c0;
    for (int k = 0; k < 2 && k < n; k++) {        // prologue: stage 2 chunks
        int bn = k & 3;
        if (committed[bn] > waited[bn]) {
            mbar_wait(sb + 8 + bn * 8, waited[bn] & 1);
            waited[bn]++;
        }
        cp_chunk(c0 + k, splitc, Ah0, Al0, lda0, Ah1, Al1, lda1,
                 Bh0, Bl0, ldb0, Bh1, Bl1, ldb1,
                 sb + 1024 + bn * 49152, tid);
        asm volatile("cp.async.commit_group;" ::: "memory");
    }
    for (int c = c0; c < c1; c++) {
        const int b = (c - c0) & 3;
        if (c + 1 < c1) asm volatile("cp.async.wait_group 1;" ::: "memory");
        else            asm volatile("cp.async.wait_group 0;" ::: "memory");
        asm volatile("fence.proxy.async.shared::cta;" ::: "memory");
        __syncthreads();

        const uint32_t sA = sb + 1024 + b * 49152;
        if (tid < 32 && elect1()) {
            uint64_t dahi = sdesc(sA),          dalo = sdesc(sA + 16384);
            uint64_t dbhi = sdesc(sA + 32768),  dblo = sdesc(sA + 40960);
            #pragma unroll
            for (int s = 0; s < KC / 16; s++) {   // bf16: K=16 per mma
                uint64_t o = (uint64_t)(s << 1);  // +32B per step
                mma_bf16(tmem, dahi + o, dbhi + o, (c > c0 || s > 0) ? 1u : 0u);
                mma_bf16(tmem, dahi + o, dblo + o, 1u);
                mma_bf16(tmem, dalo + o, dbhi + o, 1u);
            }
            asm volatile(
                "tcgen05.commit.cta_group::1.mbarrier::arrive::one.shared::cluster.b64 [%0];"
                :: "r"(sb + 8 + b * 8) : "memory");
        }
        committed[b]++;

        int f = c + 2;                            // stage chunk c+2
        if (f < c1) {
            int bn = (f - c0) & 3;
            if (committed[bn] > waited[bn]) {
                mbar_wait(sb + 8 + bn * 8, waited[bn] & 1);
                waited[bn]++;
            }
            cp_chunk(f, splitc, Ah0, Al0, lda0, Ah1, Al1, lda1,
                     Bh0, Bl0, ldb0, Bh1, Bl1, ldb1,
                     sb + 1024 + bn * 49152, tid);
            asm volatile("cp.async.commit_group;" ::: "memory");
        }
    }
    #pragma unroll
    for (int b = 0; b < 4; b++) {                 // drain MMAs
        if (committed[b] > waited[b]) {
            mbar_wait(sb + 8 + b * 8, waited[b] & 1);
            waited[b]++;
        }
    }
    asm volatile("tcgen05.fence::after_thread_sync;" ::: "memory");

    if (tid < 128) {
        uint32_t d0[32], d1[32];
        LDTM32(d0, tmem);
        LDTM32(d1, tmem + 32);
        asm volatile("tcgen05.wait::ld.sync.aligned;" ::: "memory");
        asm volatile("tcgen05.fence::before_thread_sync;" ::: "memory");
        float* drow = dst + (size_t)tid * ldd;
        #pragma unroll
        for (int c4 = 0; c4 < 8; c4++) {
            *reinterpret_cast<float4*>(drow + c4 * 4) = make_float4(
                __uint_as_float(d0[c4 * 4 + 0]), __uint_as_float(d0[c4 * 4 + 1]),
                __uint_as_float(d0[c4 * 4 + 2]), __uint_as_float(d0[c4 * 4 + 3]));
            *reinterpret_cast<float4*>(drow + 32 + c4 * 4) = make_float4(
                __uint_as_float(d1[c4 * 4 + 0]), __uint_as_float(d1[c4 * 4 + 1]),
                __uint_as_float(d1[c4 * 4 + 2]), __uint_as_float(d1[c4 * 4 + 3]));
        }
    }
    __syncthreads();
#else
    // ---- SIMT fallback (base-arch pass only; never selected at runtime) ----
    (void)sb; (void)tmem; (void)committed; (void)waited;
    if (tid < 128) {
        float acc[64];
        #pragma unroll
        for (int j = 0; j < 64; j++) acc[j] = 0.f;
        for (int c = c0; c < c1; c++) {
            const bf16 *Ah, *Al, *Bh, *Bl; int la, lb; size_t ko;
            if (c < splitc) { Ah = Ah0; Al = Al0; la = lda0; Bh = Bh0; Bl = Bl0;
                              lb = ldb0; ko = (size_t)c * KC; }
            else            { Ah = Ah1; Al = Al1; la = lda1; Bh = Bh1; Bl = Bl1;
                              lb = ldb1; ko = (size_t)(c - splitc) * KC; }
            for (int k = 0; k < KC; k++) {
                float a = __bfloat162float(Ah[(size_t)tid * la + ko + k]) +
                          __bfloat162float(Al[(size_t)tid * la + ko + k]);
                for (int j = 0; j < 64; j++)
                    acc[j] += a * (__bfloat162float(Bh[(size_t)j * lb + ko + k]) +
                                   __bfloat162float(Bl[(size_t)j * lb + ko + k]));
            }
        }
        float* drow = dst + (size_t)tid * ldd;
        for (int j = 0; j < 64; j++) drow[j] = acc[j];
    }
    __syncthreads();
#endif
}

// ---------------------------------------------------------------------------
__global__ void __launch_bounds__(NTH, 1) k_rnn(
    const float* __restrict__ bih1, const float* __restrict__ bhh1,
    const float* __restrict__ bih2, const float* __restrict__ bhh2,
    const float* __restrict__ bg,
    const float* __restrict__ bo1, const float* __restrict__ bo2,
    float* __restrict__ out)
{
    extern __shared__ char dynsm[];
    const uint32_t sb = cvta_s(dynsm);
    const int tid = threadIdx.x;
    const int u = blockIdx.x;
    unsigned epoch = g_epoch_base;
    uint32_t committed[4] = {0u, 0u, 0u, 0u}, waited[4] = {0u, 0u, 0u, 0u};
    uint32_t tmem = 0;

#if HAS_TCGEN05
    if (tid < 32) {
        asm volatile(
            "tcgen05.alloc.cta_group::1.sync.aligned.shared::cta.b32 [%0], %1;"
            :: "r"(sb), "r"(64u) : "memory");
        asm volatile("tcgen05.relinquish_alloc_permit.cta_group::1.sync.aligned;");
    }
    if (tid == 0) {
        #pragma unroll
        for (int b = 0; b < 4; b++)
            asm volatile("mbarrier.init.shared.b64 [%0], 1;"
                         :: "r"(sb + 8 + b * 8) : "memory");
    }
    __syncthreads();
    asm volatile("ld.shared.b32 %0, [%1];" : "=r"(tmem) : "r"(sb));
#endif

    const int n4 = BB * HH / 4;

    for (int i = u * NTH + tid; i < BB * HH; i += NCTA * NTH) {
        h1hi[i] = __float2bfloat16(0.f); h1lo[i] = __float2bfloat16(0.f);
        h2hi[i] = __float2bfloat16(0.f); h2lo[i] = __float2bfloat16(0.f);
        g_u[i] = 1.f;
    }
    gsync(epoch, u, tid);

    for (int t = 0; t <= TT; t++) {
        // ===== phase 1: GEMMs on h1(t-1), h2(t-1), x(t) =====
        if (u < 48 && t < TT) {
            int jt = u / 3, s = u % 3;
            run_unit(cT1[s], cT1[s + 1], 1,
                     xhi + (size_t)t * 64, xlo + (size_t)t * 64, TT * II,
                     h1hi, h1lo, HH,
                     Wih1hi + (size_t)jt * 64 * II, Wih1lo + (size_t)jt * 64 * II, II,
                     Whh1hi + (size_t)jt * 64 * HH, Whh1lo + (size_t)jt * 64 * HH, HH,
                     sb, tmem,
                     pH1 + (size_t)s * BB * HH + jt * 64, HH,
                     tid, committed, waited);
        } else if (u < 96 && t < TT) {
            int idx = u - 48, jt = idx / 3, s = idx % 3;
            run_unit(cT2[s], cT2[s + 1], 0,
                     nullptr, nullptr, 0, h2hi, h2lo, HH,
                     nullptr, nullptr, 0,
                     Wghi + (size_t)jt * 64 * 2048 + 1024,
                     Wglo + (size_t)jt * 64 * 2048 + 1024, 2048,
                     sb, tmem,
                     pG + (size_t)s * BB * HH + jt * 64, HH,
                     tid, committed, waited);
        } else if (u < 144 && t < TT) {
            int idx = u - 96, jt = idx / 3, s = idx % 3;
            run_unit(cT2[s], cT2[s + 1], 0,
                     nullptr, nullptr, 0, h2hi, h2lo, HH,
                     nullptr, nullptr, 0,
                     Whh2hi + (size_t)jt * 64 * HH, Whh2lo + (size_t)jt * 64 * HH, HH,
                     sb, tmem,
                     pH2 + (size_t)s * BB * HH + jt * 64, HH,
                     tid, committed, waited);
        } else if (u >= 144 && u < 147) {
            int s = u - 144;
            run_unit(cT4[s], cT4[s + 1], 0,
                     nullptr, nullptr, 0, h2hi, h2lo, HH,
                     nullptr, nullptr, 0, Wo2hi, Wo2lo, HH,
                     sb, tmem,
                     pO + (size_t)s * BB * OO, OO,
                     tid, committed, waited);
        }
        gsync(epoch, u, tid);

        // ===== reduce 1: h1(t) split; u(t-1); out(t-1) =====
        if (t < TT) {
            for (int i4 = u * NTH + tid; i4 < n4; i4 += NCTA * NTH) {
                int j0 = (i4 << 2) & (HH - 1);
                float4 b1 = *reinterpret_cast<const float4*>(bih1 + j0);
                float4 b2 = *reinterpret_cast<const float4*>(bhh1 + j0);
                float4 s = make_float4(b1.x + b2.x, b1.y + b2.y,
                                       b1.z + b2.z, b1.w + b2.w);
                #pragma unroll
                for (int ss = 0; ss < 3; ss++) {
                    float4 p = __ldcg(&reinterpret_cast<const float4*>(pH1)[ss * n4 + i4]);
                    s.x += p.x; s.y += p.y; s.z += p.z; s.w += p.w;
                }
                float4 v = make_float4(tanhf(s.x), tanhf(s.y), tanhf(s.z), tanhf(s.w));
                bf16 hx, lx, hy, ly, hz, lz, hw, lw;
                splitbf(v.x, hx, lx); splitbf(v.y, hy, ly);
                splitbf(v.z, hz, lz); splitbf(v.w, hw, lw);
                uint2 wh, wl;
                wh.x = pack2(__bfloat162float(hx), __bfloat162float(hy));
                wh.y = pack2(__bfloat162float(hz), __bfloat162float(hw));
                wl.x = pack2(__bfloat162float(lx), __bfloat162float(ly));
                wl.y = pack2(__bfloat162float(lz), __bfloat162float(lw));
                *reinterpret_cast<uint2*>(&h1hi[i4 * 4]) = wh;
                *reinterpret_cast<uint2*>(&h1lo[i4 * 4]) = wl;
            }
        }
        if (t > 0 && t < TT) {
            for (int i4 = u * NTH + tid; i4 < n4; i4 += NCTA * NTH) {
                int j0 = (i4 << 2) & (HH - 1);
                float4 s = *reinterpret_cast<const float4*>(bg + j0);
                #pragma unroll
                for (int ss = 0; ss < 7; ss++) {
                    float4 p = __ldcg(&reinterpret_cast<const float4*>(pG)[ss * n4 + i4]);
                    s.x += p.x; s.y += p.y; s.z += p.z; s.w += p.w;
                }
                float4 r;
                r.x = 1.f / (1.f + expf(-s.x));
                r.y = 1.f / (1.f + expf(-s.y));
                r.z = 1.f / (1.f + expf(-s.z));
                r.w = 1.f / (1.f + expf(-s.w));
                reinterpret_cast<float4*>(g_u)[i4] = r;
            }
        }
        if (t > 0) {
            for (int i4 = u * NTH + tid; i4 < BB * OO / 4; i4 += NCTA * NTH) {
                int b = i4 >> 4;
                int o4 = (i4 & 15) * 4;
                float4 s1 = *reinterpret_cast<const float4*>(bo1 + o4);
                float4 s2 = *reinterpret_cast<const float4*>(bo2 + o4);
                #pragma unroll
                for (int ss = 3; ss < 7; ss++) {
                    float4 p = __ldcg(reinterpret_cast<const float4*>(
                        pO + (size_t)ss * BB * OO + b * OO + o4));
                    s1.x += p.x; s1.y += p.y; s1.z += p.z; s1.w += p.w;
                }
                #pragma unroll
                for (int ss = 0; ss < 3; ss++) {
                    float4 p = __ldcg(reinterpret_cast<const float4*>(
                        pO + (size_t)ss * BB * OO + b * OO + o4));
                    s2.x += p.x; s2.y += p.y; s2.z += p.z; s2.w += p.w;
                }
                float4 r;
                r.x = tanhf(s1.x) + tanhf(s2.x);
                r.y = tanhf(s1.y) + tanhf(s2.y);
                r.z = tanhf(s1.z) + tanhf(s2.z);
                r.w = tanhf(s1.w) + tanhf(s2.w);
                *reinterpret_cast<float4*>(
                    out + (size_t)b * TT * OO + (t - 1) * OO + o4) = r;
            }
        }
        if (t == TT) break;
        gsync(epoch, u, tid);

        // ===== phase 2: GEMMs on h1(t) =====
        if (u < 64) {
            int jt = u >> 2, s = u & 3;
            run_unit(s * 4, s * 4 + 4, 0,
                     nullptr, nullptr, 0, h1hi, h1lo, HH,
                     nullptr, nullptr, 0,
                     Wih2hi + (size_t)jt * 64 * HH, Wih2lo + (size_t)jt * 64 * HH, HH,
                     sb, tmem,
                     pH2 + (size_t)(3 + s) * BB * HH + jt * 64, HH,
                     tid, committed, waited);
        } else if (u < 128) {
            int idx = u - 64, jt = idx >> 2, s = idx & 3;
            run_unit(s * 4, s * 4 + 4, 0,
                     nullptr, nullptr, 0, h1hi, h1lo, HH,
                     nullptr, nullptr, 0,
                     Wghi + (size_t)jt * 64 * 2048, Wglo + (size_t)jt * 64 * 2048, 2048,
                     sb, tmem,
                     pG + (size_t)(3 + s) * BB * HH + jt * 64, HH,
                     tid, committed, waited);
        } else if (u < 132) {
            int s = u - 128;
            run_unit(s * 4, s * 4 + 4, 0,
                     nullptr, nullptr, 0, h1hi, h1lo, HH,
                     nullptr, nullptr, 0, Wo1hi, Wo1lo, HH,
                     sb, tmem,
                     pO + (size_t)(3 + s) * BB * OO, OO,
                     tid, committed, waited);
        }
        gsync(epoch, u, tid);

        // ===== reduce 2: h2(t) = u(t-1)*tanh(.) + (1-u(t-1))*h2(t-1) =====
        for (int i4 = u * NTH + tid; i4 < n4; i4 += NCTA * NTH) {
            int j0 = (i4 << 2) & (HH - 1);
            float4 b1 = *reinterpret_cast<const float4*>(bih2 + j0);
            float4 b2 = *reinterpret_cast<const float4*>(bhh2 + j0);
            float4 s = make_float4(b1.x + b2.x, b1.y + b2.y,
                                   b1.z + b2.z, b1.w + b2.w);
            #pragma unroll
            for (int ss = 0; ss < 7; ss++) {
                float4 p = __ldcg(&reinterpret_cast<const float4*>(pH2)[ss * n4 + i4]);
                s.x += p.x; s.y += p.y; s.z += p.z; s.w += p.w;
            }
            float4 uu = __ldcg(&reinterpret_cast<const float4*>(g_u)[i4]);
            uint2 ph = *reinterpret_cast<const uint2*>(&h2hi[i4 * 4]);
            uint2 pl = *reinterpret_cast<const uint2*>(&h2lo[i4 * 4]);
            __nv_bfloat162 ph0 = *reinterpret_cast<__nv_bfloat162*>(&ph.x);
            __nv_bfloat162 ph1v = *reinterpret_cast<__nv_bfloat162*>(&ph.y);
            __nv_bfloat162 pl0 = *reinterpret_cast<__nv_bfloat162*>(&pl.x);
            __nv_bfloat162 pl1v = *reinterpret_cast<__nv_bfloat162*>(&pl.y);
            float hp_x = __bfloat162float(ph0.x) + __bfloat162float(pl0.x);
            float hp_y = __bfloat162float(ph0.y) + __bfloat162float(pl0.y);
            float hp_z = __bfloat162float(ph1v.x) + __bfloat162float(pl1v.x);
            float hp_w = __bfloat162float(ph1v.y) + __bfloat162float(pl1v.y);
            float4 v;
            v.x = uu.x * tanhf(s.x) + (1.f - uu.x) * hp_x;
            v.y = uu.y * tanhf(s.y) + (1.f - uu.y) * hp_y;
            v.z = uu.z * tanhf(s.z) + (1.f - uu.z) * hp_z;
            v.w = uu.w * tanhf(s.w) + (1.f - uu.w) * hp_w;
            bf16 hx, lx, hy, ly, hz, lz, hw, lw;
            splitbf(v.x, hx, lx); splitbf(v.y, hy, ly);
            splitbf(v.z, hz, lz); splitbf(v.w, hw, lw);
            uint2 wh, wl;
            wh.x = pack2(__bfloat162float(hx), __bfloat162float(hy));
            wh.y = pack2(__bfloat162float(hz), __bfloat162float(hw));
            wl.x = pack2(__bfloat162float(lx), __bfloat162float(ly));
            wl.y = pack2(__bfloat162float(lz), __bfloat162float(lw));
            *reinterpret_cast<uint2*>(&h2hi[i4 * 4]) = wh;
            *reinterpret_cast<uint2*>(&h2lo[i4 * 4]) = wl;
        }
        gsync(epoch, u, tid);
    }

    if (u == 0 && tid == 0) g_epoch_base = epoch;

    __syncthreads();
#if HAS_TCGEN05
    if (tid < 32) {
        asm volatile("tcgen05.dealloc.cta_group::1.sync.aligned.b32 %0, %1;"
                     :: "r"(tmem), "r"(64u));
    }
#endif
}

// ---------------------------------------------------------------------------
extern "C" void kernel_launch(void* const* d_in, const int* in_sizes, int n_in,
                              void* d_out, int out_size) {
    const float* x    = (const float*)d_in[0];
    const float* Wih1 = (const float*)d_in[1];
    const float* bih1 = (const float*)d_in[2];
    const float* Whh1 = (const float*)d_in[3];
    const float* bhh1 = (const float*)d_in[4];
    const float* Wih2 = (const float*)d_in[5];
    const float* bih2 = (const float*)d_in[6];
    const float* Whh2 = (const float*)d_in[7];
    const float* bhh2 = (const float*)d_in[8];
    const float* Wg   = (const float*)d_in[9];
    const float* bg   = (const float*)d_in[10];
    const float* Wo1  = (const float*)d_in[11];
    const float* bo1  = (const float*)d_in[12];
    const float* Wo2  = (const float*)d_in[13];
    const float* bo2  = (const float*)d_in[14];
    float* out = (float*)d_out;

    cudaFuncSetAttribute(k_rnn, cudaFuncAttributeMaxDynamicSharedMemorySize,
                         SMEM_BYTES);

    k_prepx<<<(BB * TT * II + 255) / 256, 256>>>(x);
    k_prepw_all<<<1024, 256>>>(Wih1, Whh1, Wih2, Whh2, Wg, Wo1, Wo2);
    k_rnn<<<NCTA, NTH, SMEM_BYTES>>>(bih1, bhh1, bih2, bhh2, bg, bo1, bo2, out);
}